// round 15
// baseline (speedup 1.0000x reference)
#include <cuda_runtime.h>
#include <cuda_fp16.h>
#include <math.h>
#include <stdint.h>

#define NN 100000
#define NE 1600000
#define NF 133
#define HD 128
#define SA 36    // As row stride (floats): %32==4 -> conflict-free A frag reads
#define SB 136   // Bs row stride (floats): %32==8 -> conflict-free B frag reads

// ---- scratch (device globals) ----
__device__ __half d_gh[NN * HD];   // g = dis[n]*(h@W)[n], fp16 for gather bandwidth
__device__ float d_h[NN * HD];     // hidden activations between layers (fp32)
__device__ int   d_cnt[NN];
__device__ int   d_rowptr[NN + 1];
__device__ int   d_head[NN];
__device__ int   d_col[NE];
__device__ float d_dis[NN];

// ---------------- preprocessing ----------------

__global__ void zero_cnt_k() {
    int i = blockIdx.x * blockDim.x + threadIdx.x;
    if (i < NN) d_cnt[i] = 0;
}

__global__ void count_k(const int* __restrict__ ei) {
    int e = (blockIdx.x * blockDim.x + threadIdx.x) * 4;
    if (e < NE) {   // NE % 4 == 0
        int4 d = *(const int4*)&ei[NE + e];
        atomicAdd(&d_cnt[d.x], 1);
        atomicAdd(&d_cnt[d.y], 1);
        atomicAdd(&d_cnt[d.z], 1);
        atomicAdd(&d_cnt[d.w], 1);
    }
}

__global__ void scan_k() {
    __shared__ int sums[1024];
    int t = threadIdx.x;
    const int CH = (NN + 1023) / 1024;
    int lo = t * CH;
    int hi = lo + CH; if (hi > NN) hi = NN;
    int s = 0;
    for (int i = lo; i < hi; i++) s += d_cnt[i];
    sums[t] = s;
    __syncthreads();
    for (int off = 1; off < 1024; off <<= 1) {
        int v = 0;
        if (t >= off) v = sums[t - off];
        __syncthreads();
        sums[t] += v;
        __syncthreads();
    }
    int run = sums[t] - s;
    for (int i = lo; i < hi; i++) {
        int c = d_cnt[i];
        d_rowptr[i] = run;
        d_head[i]   = run;
        d_dis[i]    = rsqrtf((float)c + 1.0f);
        run += c;
    }
    if (t == 1023) d_rowptr[NN] = run;
}

__global__ void fill_k(const int* __restrict__ ei) {
    int e = (blockIdx.x * blockDim.x + threadIdx.x) * 2;
    if (e < NE) {   // NE % 2 == 0
        int2 s = *(const int2*)&ei[e];
        int2 d = *(const int2*)&ei[NE + e];
        int p0 = atomicAdd(&d_head[d.x], 1);
        d_col[p0] = s.x;
        int p1 = atomicAdd(&d_head[d.y], 1);
        d_col[p1] = s.y;
    }
}

// ---------------- per-layer GEMM (tf32 tensor cores) ----------------

__device__ __forceinline__ float to_tf32(float x) {
    float y;
    asm("cvt.rna.tf32.f32 %0, %1;" : "=f"(y) : "f"(x));
    return y;
}

__global__ __launch_bounds__(256, 2)
void gemm_k(const float* __restrict__ Hext,
            const float* __restrict__ W, int K) {
    __shared__ float As[128 * SA];  // [row][k], k-chunk of 32
    __shared__ float Bs[32 * SB];   // [k][col]
    const float* H = Hext ? Hext : d_h;

    int tid  = threadIdx.x;
    int wid  = tid >> 5;
    int lane = tid & 31;
    int g    = lane >> 2;
    int tig  = lane & 3;
    int wm   = wid & 3;
    int wn   = wid >> 2;
    int m0   = blockIdx.x * 128;

    float acc[2][8][4];
    #pragma unroll
    for (int mt = 0; mt < 2; mt++)
        #pragma unroll
        for (int nf = 0; nf < 8; nf++)
            #pragma unroll
            for (int c = 0; c < 4; c++) acc[mt][nf][c] = 0.0f;

    int nkc = (K + 31) / 32;
    for (int kc = 0; kc < nkc; kc++) {
        int k0 = kc * 32;
        #pragma unroll
        for (int i = tid; i < 128 * 32; i += 256) {
            int r = i >> 5, kk = i & 31;
            int gm = m0 + r, gk = k0 + kk;
            float v = (gm < NN && gk < K) ? H[(size_t)gm * K + gk] : 0.0f;
            As[r * SA + kk] = to_tf32(v);
        }
        #pragma unroll
        for (int i = tid; i < 32 * 128; i += 256) {
            int kk = i >> 7, c = i & 127;
            int gk = k0 + kk;
            float v = (gk < K) ? W[gk * HD + c] : 0.0f;
            Bs[kk * SB + c] = to_tf32(v);
        }
        __syncthreads();

        #pragma unroll
        for (int ks = 0; ks < 4; ks++) {
            int kb = ks * 8;
            uint32_t a[2][4];
            #pragma unroll
            for (int mt = 0; mt < 2; mt++) {
                int rb = wm * 32 + mt * 16;
                a[mt][0] = __float_as_uint(As[(rb + g)     * SA + kb + tig]);
                a[mt][1] = __float_as_uint(As[(rb + g + 8) * SA + kb + tig]);
                a[mt][2] = __float_as_uint(As[(rb + g)     * SA + kb + tig + 4]);
                a[mt][3] = __float_as_uint(As[(rb + g + 8) * SA + kb + tig + 4]);
            }
            #pragma unroll
            for (int nf = 0; nf < 8; nf++) {
                int cb = wn * 64 + nf * 8 + g;
                uint32_t b0 = __float_as_uint(Bs[(kb + tig)     * SB + cb]);
                uint32_t b1 = __float_as_uint(Bs[(kb + tig + 4) * SB + cb]);
                #pragma unroll
                for (int mt = 0; mt < 2; mt++) {
                    asm volatile(
                        "mma.sync.aligned.m16n8k8.row.col.f32.tf32.tf32.f32 "
                        "{%0,%1,%2,%3}, {%4,%5,%6,%7}, {%8,%9}, {%0,%1,%2,%3};"
                        : "+f"(acc[mt][nf][0]), "+f"(acc[mt][nf][1]),
                          "+f"(acc[mt][nf][2]), "+f"(acc[mt][nf][3])
                        : "r"(a[mt][0]), "r"(a[mt][1]), "r"(a[mt][2]), "r"(a[mt][3]),
                          "r"(b0), "r"(b1));
                }
            }
        }
        __syncthreads();
    }

    #pragma unroll
    for (int mt = 0; mt < 2; mt++) {
        int r0 = m0 + wm * 32 + mt * 16 + g;
        int r1 = r0 + 8;
        float sc0 = (r0 < NN) ? d_dis[r0] : 0.0f;
        float sc1 = (r1 < NN) ? d_dis[r1] : 0.0f;
        #pragma unroll
        for (int nf = 0; nf < 8; nf++) {
            int col = wn * 64 + nf * 8 + 2 * tig;
            if (r0 < NN) {
                __half2 h = __floats2half2_rn(acc[mt][nf][0] * sc0,
                                              acc[mt][nf][1] * sc0);
                *(__half2*)&d_gh[(size_t)r0 * HD + col] = h;
            }
            if (r1 < NN) {
                __half2 h = __floats2half2_rn(acc[mt][nf][2] * sc1,
                                              acc[mt][nf][3] * sc1);
                *(__half2*)&d_gh[(size_t)r1 * HD + col] = h;
            }
        }
    }
}

// ---------------- per-layer aggregation + bias + tanh ----------------
// one warp per node. Neighbor rows staged into SMEM via cp.async.cg
// (LDGSTS: L2 -> smem, bypasses L1/MSHR and the register scoreboard).
// Chunks of 8 rows (2KB), double-buffered. fp32 add order identical to
// R12 (sequential edge order per node) -> bit-identical rounding.

__device__ __forceinline__ void cp16(uint32_t saddr, const void* gptr) {
    asm volatile("cp.async.cg.shared.global [%0], [%1], 16;"
                 :: "r"(saddr), "l"(gptr));
}

__global__ __launch_bounds__(256)
void agg_k(const float* __restrict__ bias,
           float* __restrict__ outp) {
    __shared__ __align__(16) char stage[8][2][2048];  // [warp][buf][8 rows * 256B]
    int wlocal = threadIdx.x >> 5;
    int gw = (blockIdx.x * blockDim.x + threadIdx.x) >> 5;
    int lane = threadIdx.x & 31;
    if (gw >= NN) return;
    float* out = outp ? outp : d_h;

    const uint2* gh  = (const uint2*)d_gh;   // 8B units, 32 per row
    const char*  ghb = (const char*)d_gh;
    int n = gw;
    float2 acc0, acc1;
    {   // self term
        uint2 raw = gh[(size_t)n * 32 + lane];
        acc0 = __half22float2(*(const __half2*)&raw.x);
        acc1 = __half22float2(*(const __half2*)&raw.y);
    }

    int lo = d_rowptr[n];
    int hi = d_rowptr[n + 1];
    int deg = hi - lo;
    int nch = deg >> 3;             // full chunks of 8 edges
    int sub = lane & 15;            // 16B slot within a row
    int rhalf = lane >> 4;          // row parity within a pair
    uint32_t sb = (uint32_t)__cvta_generic_to_shared(&stage[wlocal][0][0]);

    if (nch > 0) {
        // --- stage chunk 0 ---
        {
            int e0 = lo;
            int myi = __ldg(&d_col[e0 + (lane & 7)]);
            #pragma unroll
            for (int i = 0; i < 4; i++) {
                int r = 2 * i + rhalf;
                int s = __shfl_sync(0xffffffffu, myi, r);
                cp16(sb + r * 256 + sub * 16, ghb + (size_t)s * 256 + sub * 16);
            }
            asm volatile("cp.async.commit_group;");
        }
        for (int c = 0; c < nch; c++) {
            if (c + 1 < nch) {   // stage next chunk into other buffer
                int e0 = lo + (c + 1) * 8;
                int myi = __ldg(&d_col[e0 + (lane & 7)]);
                uint32_t bufo = ((c + 1) & 1) * 2048;
                #pragma unroll
                for (int i = 0; i < 4; i++) {
                    int r = 2 * i + rhalf;
                    int s = __shfl_sync(0xffffffffu, myi, r);
                    cp16(sb + bufo + r * 256 + sub * 16,
                         ghb + (size_t)s * 256 + sub * 16);
                }
                asm volatile("cp.async.commit_group;");
                asm volatile("cp.async.wait_group 1;");
            } else {
                asm volatile("cp.async.wait_group 0;");
            }
            __syncwarp();
            const uint2* rows = (const uint2*)&stage[wlocal][c & 1][0];
            #pragma unroll
            for (int j = 0; j < 8; j++) {
                uint2 r = rows[j * 32 + lane];
                float2 v;
                v = __half22float2(*(const __half2*)&r.x); acc0.x += v.x; acc0.y += v.y;
                v = __half22float2(*(const __half2*)&r.y); acc1.x += v.x; acc1.y += v.y;
            }
            __syncwarp();
        }
    }
    // tail (< 8 edges)
    for (int e = lo + nch * 8; e < hi; e++) {
        int s = __ldg(&d_col[e]);
        uint2 r = __ldg(&gh[(size_t)s * 32 + lane]);
        float2 v;
        v = __half22float2(*(const __half2*)&r.x); acc0.x += v.x; acc0.y += v.y;
        v = __half22float2(*(const __half2*)&r.y); acc1.x += v.x; acc1.y += v.y;
    }

    float sc = d_dis[n];
    float4 b = *(const float4*)&bias[lane * 4];
    float4 o;
    o.x = tanhf(sc * acc0.x + b.x);
    o.y = tanhf(sc * acc0.y + b.y);
    o.z = tanhf(sc * acc1.x + b.z);
    o.w = tanhf(sc * acc1.y + b.w);
    *(float4*)&out[(size_t)n * HD + lane * 4] = o;
}

// ---------------- launch ----------------
// NOTE: gemm0 launched BEFORE fill_k (it only needs d_dis from scan_k)
// so the ncu -s 5 -c 1 window lands on gemm_k instead of fill_k.

extern "C" void kernel_launch(void* const* d_in, const int* in_sizes, int n_in,
                              void* d_out, int out_size) {
    const float* x  = (const float*)d_in[0];   // [NN, 133]
    const int*   ei = (const int*)d_in[1];     // [2, NE] int32
    const float* W[4] = {(const float*)d_in[2], (const float*)d_in[4],
                         (const float*)d_in[6], (const float*)d_in[8]};
    const float* B[4] = {(const float*)d_in[3], (const float*)d_in[5],
                         (const float*)d_in[7], (const float*)d_in[9]};
    float* out = (float*)d_out;

    const int GEMM_BLOCKS = (NN + 127) / 128;
    const int AGG_BLOCKS  = (NN * 32 + 255) / 256;

    zero_cnt_k<<<(NN + 255) / 256, 256>>>();
    count_k<<<(NE / 4 + 255) / 256, 256>>>(ei);
    scan_k<<<1, 1024>>>();
    gemm_k<<<GEMM_BLOCKS, 256>>>(x, W[0], NF);     // needs only d_dis
    fill_k<<<(NE / 2 + 255) / 256, 256>>>(ei);
    agg_k<<<AGG_BLOCKS, 256>>>(B[0], nullptr);
    gemm_k<<<GEMM_BLOCKS, 256>>>(nullptr, W[1], HD);
    agg_k<<<AGG_BLOCKS, 256>>>(B[1], nullptr);
    gemm_k<<<GEMM_BLOCKS, 256>>>(nullptr, W[2], HD);
    agg_k<<<AGG_BLOCKS, 256>>>(B[2], nullptr);
    gemm_k<<<GEMM_BLOCKS, 256>>>(nullptr, W[3], HD);
    agg_k<<<AGG_BLOCKS, 256>>>(B[3], out);
}

// round 17
// speedup vs baseline: 1.1385x; 1.1385x over previous
#include <cuda_runtime.h>
#include <cuda_fp16.h>
#include <math.h>
#include <stdint.h>

#define NN 100000
#define NE 1600000
#define NF 133
#define HD 128
#define SA 36    // As row stride (floats): %32==4 -> conflict-free A frag reads
#define SB 136   // Bs row stride (floats): %32==8 -> conflict-free B frag reads

// ---- scratch (device globals) ----
__device__ __half d_gh[NN * HD];        // g = dis[n]*(h@W)[n], fp16
__device__ float d_h[NN * HD];          // activations, tf32-rounded values
__device__ float d_w32[3][HD * HD];     // W1..W3 pre-rounded to tf32
__device__ int   d_cnt[NN];
__device__ int   d_rowptr[NN + 1];
__device__ int   d_head[NN];
__device__ int   d_col[NE];
__device__ float d_dis[NN];

__device__ __forceinline__ float to_tf32(float x) {
    float y;
    asm("cvt.rna.tf32.f32 %0, %1;" : "=f"(y) : "f"(x));
    return y;
}

// ---------------- preprocessing ----------------

__global__ void zero_cnt_k() {
    int i = blockIdx.x * blockDim.x + threadIdx.x;
    if (i < NN) d_cnt[i] = 0;
}

__global__ void count_k(const int* __restrict__ ei) {
    int e = (blockIdx.x * blockDim.x + threadIdx.x) * 4;
    if (e < NE) {   // NE % 4 == 0
        int4 d = *(const int4*)&ei[NE + e];
        atomicAdd(&d_cnt[d.x], 1);
        atomicAdd(&d_cnt[d.y], 1);
        atomicAdd(&d_cnt[d.z], 1);
        atomicAdd(&d_cnt[d.w], 1);
    }
}

__global__ void scan_k() {
    __shared__ int sums[1024];
    int t = threadIdx.x;
    const int CH = (NN + 1023) / 1024;
    int lo = t * CH;
    int hi = lo + CH; if (hi > NN) hi = NN;
    int s = 0;
    for (int i = lo; i < hi; i++) s += d_cnt[i];
    sums[t] = s;
    __syncthreads();
    for (int off = 1; off < 1024; off <<= 1) {
        int v = 0;
        if (t >= off) v = sums[t - off];
        __syncthreads();
        sums[t] += v;
        __syncthreads();
    }
    int run = sums[t] - s;
    for (int i = lo; i < hi; i++) {
        int c = d_cnt[i];
        d_rowptr[i] = run;
        d_head[i]   = run;
        d_dis[i]    = rsqrtf((float)c + 1.0f);
        run += c;
    }
    if (t == 1023) d_rowptr[NN] = run;
}

__global__ void fill_k(const int* __restrict__ ei) {
    int e = (blockIdx.x * blockDim.x + threadIdx.x) * 2;
    if (e < NE) {   // NE % 2 == 0
        int2 s = *(const int2*)&ei[e];
        int2 d = *(const int2*)&ei[NE + e];
        int p0 = atomicAdd(&d_head[d.x], 1);
        d_col[p0] = s.x;
        int p1 = atomicAdd(&d_head[d.y], 1);
        d_col[p1] = s.y;
    }
}

__global__ void cvtw_k(const float* __restrict__ w1,
                       const float* __restrict__ w2,
                       const float* __restrict__ w3) {
    int i = blockIdx.x * blockDim.x + threadIdx.x;
    if (i < HD * HD) {
        d_w32[0][i] = to_tf32(w1[i]);
        d_w32[1][i] = to_tf32(w2[i]);
        d_w32[2][i] = to_tf32(w3[i]);
    }
}

// ---------------- layer-0 GEMM (scalar staging, K=133) ----------------

__global__ __launch_bounds__(256, 2)
void gemm_k(const float* __restrict__ H,
            const float* __restrict__ W, int K) {
    __shared__ float As[128 * SA];
    __shared__ float Bs[32 * SB];

    int tid  = threadIdx.x;
    int wid  = tid >> 5;
    int lane = tid & 31;
    int g    = lane >> 2;
    int tig  = lane & 3;
    int wm   = wid & 3;
    int wn   = wid >> 2;
    int m0   = blockIdx.x * 128;

    float acc[2][8][4];
    #pragma unroll
    for (int mt = 0; mt < 2; mt++)
        #pragma unroll
        for (int nf = 0; nf < 8; nf++)
            #pragma unroll
            for (int c = 0; c < 4; c++) acc[mt][nf][c] = 0.0f;

    int nkc = (K + 31) / 32;
    for (int kc = 0; kc < nkc; kc++) {
        int k0 = kc * 32;
        #pragma unroll
        for (int i = tid; i < 128 * 32; i += 256) {
            int r = i >> 5, kk = i & 31;
            int gm = m0 + r, gk = k0 + kk;
            float v = (gm < NN && gk < K) ? H[(size_t)gm * K + gk] : 0.0f;
            As[r * SA + kk] = to_tf32(v);
        }
        #pragma unroll
        for (int i = tid; i < 32 * 128; i += 256) {
            int kk = i >> 7, c = i & 127;
            int gk = k0 + kk;
            float v = (gk < K) ? W[gk * HD + c] : 0.0f;
            Bs[kk * SB + c] = to_tf32(v);
        }
        __syncthreads();

        #pragma unroll
        for (int ks = 0; ks < 4; ks++) {
            int kb = ks * 8;
            uint32_t a[2][4];
            #pragma unroll
            for (int mt = 0; mt < 2; mt++) {
                int rb = wm * 32 + mt * 16;
                a[mt][0] = __float_as_uint(As[(rb + g)     * SA + kb + tig]);
                a[mt][1] = __float_as_uint(As[(rb + g + 8) * SA + kb + tig]);
                a[mt][2] = __float_as_uint(As[(rb + g)     * SA + kb + tig + 4]);
                a[mt][3] = __float_as_uint(As[(rb + g + 8) * SA + kb + tig + 4]);
            }
            #pragma unroll
            for (int nf = 0; nf < 8; nf++) {
                int cb = wn * 64 + nf * 8 + g;
                uint32_t b0 = __float_as_uint(Bs[(kb + tig)     * SB + cb]);
                uint32_t b1 = __float_as_uint(Bs[(kb + tig + 4) * SB + cb]);
                #pragma unroll
                for (int mt = 0; mt < 2; mt++) {
                    asm volatile(
                        "mma.sync.aligned.m16n8k8.row.col.f32.tf32.tf32.f32 "
                        "{%0,%1,%2,%3}, {%4,%5,%6,%7}, {%8,%9}, {%0,%1,%2,%3};"
                        : "+f"(acc[mt][nf][0]), "+f"(acc[mt][nf][1]),
                          "+f"(acc[mt][nf][2]), "+f"(acc[mt][nf][3])
                        : "r"(a[mt][0]), "r"(a[mt][1]), "r"(a[mt][2]), "r"(a[mt][3]),
                          "r"(b0), "r"(b1));
                }
            }
        }
        __syncthreads();
    }

    #pragma unroll
    for (int mt = 0; mt < 2; mt++) {
        int r0 = m0 + wm * 32 + mt * 16 + g;
        int r1 = r0 + 8;
        float sc0 = (r0 < NN) ? d_dis[r0] : 0.0f;
        float sc1 = (r1 < NN) ? d_dis[r1] : 0.0f;
        #pragma unroll
        for (int nf = 0; nf < 8; nf++) {
            int col = wn * 64 + nf * 8 + 2 * tig;
            if (r0 < NN) {
                __half2 h = __floats2half2_rn(acc[mt][nf][0] * sc0,
                                              acc[mt][nf][1] * sc0);
                *(__half2*)&d_gh[(size_t)r0 * HD + col] = h;
            }
            if (r1 < NN) {
                __half2 h = __floats2half2_rn(acc[mt][nf][2] * sc1,
                                              acc[mt][nf][3] * sc1);
                *(__half2*)&d_gh[(size_t)r1 * HD + col] = h;
            }
        }
    }
}

// ---------------- layers 1-3 GEMM: cp.async double-buffered, K=128 ----------------
// A = d_h (values already tf32-rounded by agg epilogue), B = d_w32[layer]
// (indexed IN DEVICE CODE -- __device__ symbols can't cross the host boundary).

#define AS_ELE (128 * SA)   // 4608
#define BS_ELE (32 * SB)    // 4352

__global__ __launch_bounds__(256, 2)
void gemmf_k(int layer) {
    extern __shared__ float sm[];
    const float* Wt = d_w32[layer];
    int tid  = threadIdx.x;
    int wid  = tid >> 5;
    int lane = tid & 31;
    int g    = lane >> 2;
    int tig  = lane & 3;
    int wm   = wid & 3;
    int wn   = wid >> 2;
    int m0   = blockIdx.x * 128;
    uint32_t sbase = (uint32_t)__cvta_generic_to_shared(sm);

    float acc[2][8][4];
    #pragma unroll
    for (int mt = 0; mt < 2; mt++)
        #pragma unroll
        for (int nf = 0; nf < 8; nf++)
            #pragma unroll
            for (int c = 0; c < 4; c++) acc[mt][nf][c] = 0.0f;

    #define STAGE(kc, buf) do {                                               \
        int k0s = (kc) * 32;                                                  \
        uint32_t ab = sbase + (buf) * (AS_ELE * 4);                           \
        uint32_t bb = sbase + (2 * AS_ELE + (buf) * BS_ELE) * 4;              \
        _Pragma("unroll")                                                     \
        for (int j = 0; j < 4; j++) {                                         \
            int c = tid + j * 256;                                            \
            int r = c >> 3, q = c & 7;                                        \
            int gm = m0 + r;                                                  \
            const float* src = d_h + (size_t)gm * HD + k0s + q * 4;           \
            int sz = (gm < NN) ? 16 : 0;                                      \
            asm volatile("cp.async.cg.shared.global [%0], [%1], 16, %2;"      \
                :: "r"(ab + (uint32_t)(r * (SA * 4) + q * 16)),               \
                   "l"(src), "r"(sz));                                        \
        }                                                                     \
        _Pragma("unroll")                                                     \
        for (int j = 0; j < 4; j++) {                                         \
            int c = tid + j * 256;                                            \
            int kk = c >> 5, c4 = c & 31;                                     \
            const float* src = Wt + (k0s + kk) * HD + c4 * 4;                 \
            asm volatile("cp.async.cg.shared.global [%0], [%1], 16;"          \
                :: "r"(bb + (uint32_t)(kk * (SB * 4) + c4 * 16)),             \
                   "l"(src));                                                 \
        }                                                                     \
        asm volatile("cp.async.commit_group;");                               \
    } while (0)

    STAGE(0, 0);
    for (int kc = 0; kc < 4; kc++) {
        if (kc < 3) {
            STAGE(kc + 1, (kc + 1) & 1);
            asm volatile("cp.async.wait_group 1;");
        } else {
            asm volatile("cp.async.wait_group 0;");
        }
        __syncthreads();
        const float* As = sm + (kc & 1) * AS_ELE;
        const float* Bs = sm + 2 * AS_ELE + (kc & 1) * BS_ELE;

        #pragma unroll
        for (int ks = 0; ks < 4; ks++) {
            int kb = ks * 8;
            uint32_t a[2][4];
            #pragma unroll
            for (int mt = 0; mt < 2; mt++) {
                int rb = wm * 32 + mt * 16;
                a[mt][0] = __float_as_uint(As[(rb + g)     * SA + kb + tig]);
                a[mt][1] = __float_as_uint(As[(rb + g + 8) * SA + kb + tig]);
                a[mt][2] = __float_as_uint(As[(rb + g)     * SA + kb + tig + 4]);
                a[mt][3] = __float_as_uint(As[(rb + g + 8) * SA + kb + tig + 4]);
            }
            #pragma unroll
            for (int nf = 0; nf < 8; nf++) {
                int cb = wn * 64 + nf * 8 + g;
                uint32_t b0 = __float_as_uint(Bs[(kb + tig)     * SB + cb]);
                uint32_t b1 = __float_as_uint(Bs[(kb + tig + 4) * SB + cb]);
                #pragma unroll
                for (int mt = 0; mt < 2; mt++) {
                    asm volatile(
                        "mma.sync.aligned.m16n8k8.row.col.f32.tf32.tf32.f32 "
                        "{%0,%1,%2,%3}, {%4,%5,%6,%7}, {%8,%9}, {%0,%1,%2,%3};"
                        : "+f"(acc[mt][nf][0]), "+f"(acc[mt][nf][1]),
                          "+f"(acc[mt][nf][2]), "+f"(acc[mt][nf][3])
                        : "r"(a[mt][0]), "r"(a[mt][1]), "r"(a[mt][2]), "r"(a[mt][3]),
                          "r"(b0), "r"(b1));
                }
            }
        }
        __syncthreads();
    }

    #pragma unroll
    for (int mt = 0; mt < 2; mt++) {
        int r0 = m0 + wm * 32 + mt * 16 + g;
        int r1 = r0 + 8;
        float sc0 = (r0 < NN) ? d_dis[r0] : 0.0f;
        float sc1 = (r1 < NN) ? d_dis[r1] : 0.0f;
        #pragma unroll
        for (int nf = 0; nf < 8; nf++) {
            int col = wn * 64 + nf * 8 + 2 * tig;
            if (r0 < NN) {
                __half2 h = __floats2half2_rn(acc[mt][nf][0] * sc0,
                                              acc[mt][nf][1] * sc0);
                *(__half2*)&d_gh[(size_t)r0 * HD + col] = h;
            }
            if (r1 < NN) {
                __half2 h = __floats2half2_rn(acc[mt][nf][2] * sc1,
                                              acc[mt][nf][3] * sc1);
                *(__half2*)&d_gh[(size_t)r1 * HD + col] = h;
            }
        }
    }
}

// ---------------- per-layer aggregation + bias + tanh (R12 form) ----------------

__global__ void agg_k(const float* __restrict__ bias,
                      float* __restrict__ outp) {
    int gw = (blockIdx.x * blockDim.x + threadIdx.x) >> 5;
    int lane = threadIdx.x & 31;
    if (gw >= NN) return;

    const uint2* gh = (const uint2*)d_gh;   // 8B units, 32 per row
    int n = gw;
    float2 acc0, acc1;
    {   // self term
        uint2 raw = gh[(size_t)n * 32 + lane];
        acc0 = __half22float2(*(const __half2*)&raw.x);
        acc1 = __half22float2(*(const __half2*)&raw.y);
    }
    int lo = d_rowptr[n];
    int hi = d_rowptr[n + 1];
    for (int base = lo; base < hi; base += 32) {
        int idx = base + lane;
        int myc = (idx < hi) ? __ldg(&d_col[idx]) : 0;
        int cnt = hi - base; if (cnt > 32) cnt = 32;
        int j = 0;
        for (; j + 4 <= cnt; j += 4) {
            int s0 = __shfl_sync(0xffffffffu, myc, j);
            int s1 = __shfl_sync(0xffffffffu, myc, j + 1);
            int s2 = __shfl_sync(0xffffffffu, myc, j + 2);
            int s3 = __shfl_sync(0xffffffffu, myc, j + 3);
            uint2 r0 = __ldg(&gh[(size_t)s0 * 32 + lane]);
            uint2 r1 = __ldg(&gh[(size_t)s1 * 32 + lane]);
            uint2 r2 = __ldg(&gh[(size_t)s2 * 32 + lane]);
            uint2 r3 = __ldg(&gh[(size_t)s3 * 32 + lane]);
            float2 v;
            v = __half22float2(*(const __half2*)&r0.x); acc0.x += v.x; acc0.y += v.y;
            v = __half22float2(*(const __half2*)&r0.y); acc1.x += v.x; acc1.y += v.y;
            v = __half22float2(*(const __half2*)&r1.x); acc0.x += v.x; acc0.y += v.y;
            v = __half22float2(*(const __half2*)&r1.y); acc1.x += v.x; acc1.y += v.y;
            v = __half22float2(*(const __half2*)&r2.x); acc0.x += v.x; acc0.y += v.y;
            v = __half22float2(*(const __half2*)&r2.y); acc1.x += v.x; acc1.y += v.y;
            v = __half22float2(*(const __half2*)&r3.x); acc0.x += v.x; acc0.y += v.y;
            v = __half22float2(*(const __half2*)&r3.y); acc1.x += v.x; acc1.y += v.y;
        }
        for (; j < cnt; j++) {
            int s = __shfl_sync(0xffffffffu, myc, j);
            uint2 r = __ldg(&gh[(size_t)s * 32 + lane]);
            float2 v;
            v = __half22float2(*(const __half2*)&r.x); acc0.x += v.x; acc0.y += v.y;
            v = __half22float2(*(const __half2*)&r.y); acc1.x += v.x; acc1.y += v.y;
        }
    }
    float sc = d_dis[n];
    float4 b = *(const float4*)&bias[lane * 4];
    float4 o;
    o.x = tanhf(sc * acc0.x + b.x);
    o.y = tanhf(sc * acc0.y + b.y);
    o.z = tanhf(sc * acc1.x + b.z);
    o.w = tanhf(sc * acc1.y + b.w);
    if (outp) {
        *(float4*)&outp[(size_t)n * HD + lane * 4] = o;
    } else {
        o.x = to_tf32(o.x); o.y = to_tf32(o.y);
        o.z = to_tf32(o.z); o.w = to_tf32(o.w);
        *(float4*)&d_h[(size_t)n * HD + lane * 4] = o;
    }
}

// ---------------- launch ----------------
// Order chosen so ncu (-s 5 -c 1) profiles agg_k (6th launch).

extern "C" void kernel_launch(void* const* d_in, const int* in_sizes, int n_in,
                              void* d_out, int out_size) {
    const float* x  = (const float*)d_in[0];   // [NN, 133]
    const int*   ei = (const int*)d_in[1];     // [2, NE] int32
    const float* W[4] = {(const float*)d_in[2], (const float*)d_in[4],
                         (const float*)d_in[6], (const float*)d_in[8]};
    const float* B[4] = {(const float*)d_in[3], (const float*)d_in[5],
                         (const float*)d_in[7], (const float*)d_in[9]};
    float* out = (float*)d_out;

    const int GEMM_BLOCKS = (NN + 127) / 128;
    const int AGG_BLOCKS  = (NN * 32 + 255) / 256;
    const int SMF = (2 * AS_ELE + 2 * BS_ELE) * 4;   // 71680 B

    cudaFuncSetAttribute(gemmf_k, cudaFuncAttributeMaxDynamicSharedMemorySize, SMF);

    zero_cnt_k<<<(NN + 255) / 256, 256>>>();                  // 1
    count_k<<<(NE / 4 + 255) / 256, 256>>>(ei);               // 2
    scan_k<<<1, 1024>>>();                                    // 3
    fill_k<<<(NE / 2 + 255) / 256, 256>>>(ei);                // 4
    gemm_k<<<GEMM_BLOCKS, 256>>>(x, W[0], NF);                // 5
    agg_k<<<AGG_BLOCKS, 256>>>(B[0], nullptr);                // 6 <- profiled
    cvtw_k<<<(HD * HD + 255) / 256, 256>>>(W[1], W[2], W[3]); // 7
    gemmf_k<<<GEMM_BLOCKS, 256, SMF>>>(0);                    // 8
    agg_k<<<AGG_BLOCKS, 256>>>(B[1], nullptr);                // 9
    gemmf_k<<<GEMM_BLOCKS, 256, SMF>>>(1);                    // 10
    agg_k<<<AGG_BLOCKS, 256>>>(B[2], nullptr);                // 11
    gemmf_k<<<GEMM_BLOCKS, 256, SMF>>>(2);                    // 12
    agg_k<<<AGG_BLOCKS, 256>>>(B[3], out);                    // 13
}